// round 1
// baseline (speedup 1.0000x reference)
#include <cuda_runtime.h>

#define CCH   512
#define HW    49
#define CHW   (CCH * HW)     // 25088 floats per sample
#define NVEC  (CHW / 4)      // 6272 float4 per sample
#define NTHR  512
#define EPS   1e-5f

__global__ __launch_bounds__(NTHR, 2)
void gate_fused_kernel(const float* __restrict__ x, float* __restrict__ out) {
    extern __shared__ float tile[];        // CHW floats (100,352 B)
    __shared__ float gateS[CCH];
    __shared__ float redA[16];
    __shared__ float redB[16];
    __shared__ float statMI[2];            // [0]=mean, [1]=inv_std

    const int n   = blockIdx.x;
    const int tid = threadIdx.x;

    const float4* __restrict__ xin  = reinterpret_cast<const float4*>(x + (size_t)n * CHW);
    float4* __restrict__       xout = reinterpret_cast<float4*>(out + (size_t)n * CHW);
    float4* tile4 = reinterpret_cast<float4*>(tile);

    // Phase 1: stage whole sample in SMEM, coalesced float4.
    #pragma unroll 4
    for (int i = tid; i < NVEC; i += NTHR)
        tile4[i] = xin[i];
    __syncthreads();

    // Phase 2: per-channel spatial mean. Thread c owns channel c.
    // Stride 49 floats between threads -> 49 mod 32 = 17 (odd) -> conflict-free.
    float s = 0.0f;
    const float* row = tile + tid * HW;
    #pragma unroll
    for (int j = 0; j < HW; j++) s += row[j];
    const float y = s * (1.0f / 49.0f);

    // Block reduce sum(y) and sum(y*y) over 512 channels.
    float a = y, b = y * y;
    #pragma unroll
    for (int off = 16; off > 0; off >>= 1) {
        a += __shfl_xor_sync(0xffffffffu, a, off);
        b += __shfl_xor_sync(0xffffffffu, b, off);
    }
    const int wid = tid >> 5, lid = tid & 31;
    if (lid == 0) { redA[wid] = a; redB[wid] = b; }
    __syncthreads();
    if (tid < 32) {
        a = (tid < 16) ? redA[tid] : 0.0f;
        b = (tid < 16) ? redB[tid] : 0.0f;
        #pragma unroll
        for (int off = 8; off > 0; off >>= 1) {
            a += __shfl_xor_sync(0xffffffffu, a, off);
            b += __shfl_xor_sync(0xffffffffu, b, off);
        }
        if (tid == 0) {
            const float m   = a * (1.0f / (float)CCH);
            const float mx2 = b * (1.0f / (float)CCH);
            float var = mx2 - m * m;
            var = var > 0.0f ? var : 0.0f;
            statMI[0] = m;
            statMI[1] = rsqrtf(var + EPS);
        }
    }
    __syncthreads();

    // Gate per channel: exp(-0.5 * C_PARAM * yn^2), C_PARAM=2 -> exp(-yn^2)
    {
        const float yn = (y - statMI[0]) * statMI[1];
        gateS[tid] = __expf(-yn * yn);
    }
    __syncthreads();

    // Phase 3: multiply from SMEM and store, coalesced float4.
    #pragma unroll 4
    for (int i = tid; i < NVEC; i += NTHR) {
        float4 v = tile4[i];
        const int e = i * 4;
        v.x *= gateS[(e + 0) / HW];
        v.y *= gateS[(e + 1) / HW];
        v.z *= gateS[(e + 2) / HW];
        v.w *= gateS[(e + 3) / HW];
        xout[i] = v;
    }
}

extern "C" void kernel_launch(void* const* d_in, const int* in_sizes, int n_in,
                              void* d_out, int out_size) {
    const float* x = (const float*)d_in[0];
    float* out = (float*)d_out;
    const int N = in_sizes[0] / CHW;   // 2048

    cudaFuncSetAttribute(gate_fused_kernel,
                         cudaFuncAttributeMaxDynamicSharedMemorySize,
                         CHW * (int)sizeof(float));
    gate_fused_kernel<<<N, NTHR, CHW * sizeof(float)>>>(x, out);
}

// round 3
// speedup vs baseline: 1.0436x; 1.0436x over previous
#include <cuda_runtime.h>

#define CCH   512
#define HW    49
#define CHW   (CCH * HW)     // 25088 floats per sample
#define NVEC  (CHW / 4)      // 6272 float4 per sample
#define NTHR  1024
#define EPS   1e-5f

// Per-thread stride in float4s = NTHR; in floats = 4096 = 83*49 + 29
#define QSTEP 83
#define RSTEP 29

__global__ __launch_bounds__(NTHR, 2)
void gate_fused_kernel(const float* __restrict__ x, float* __restrict__ out) {
    extern __shared__ float tile[];        // CHW floats (100,352 B)
    __shared__ float gateS[CCH + 8];       // pad to keep speculative q+1 read in-bounds
    __shared__ float redA[32];
    __shared__ float redB[32];
    __shared__ float statMI[2];            // [0]=mean, [1]=inv_std

    const int n   = blockIdx.x;
    const int tid = threadIdx.x;

    const float4* __restrict__ xin  = reinterpret_cast<const float4*>(x + (size_t)n * CHW);
    float4* __restrict__       xout = reinterpret_cast<float4*>(out + (size_t)n * CHW);
    float4* tile4 = reinterpret_cast<float4*>(tile);

    // Phase 1: stage whole sample in SMEM, coalesced float4. 6272/1024 = 6.125/thread.
    #pragma unroll 4
    for (int i = tid; i < NVEC; i += NTHR)
        tile4[i] = xin[i];
    __syncthreads();

    // Phase 2: per-channel spatial mean. Threads 0..511 own one channel each.
    // Stride 49 floats between threads -> 49 mod 32 odd -> conflict-free.
    float y = 0.0f;
    if (tid < CCH) {
        float s = 0.0f;
        const float* row = tile + tid * HW;
        #pragma unroll
        for (int j = 0; j < HW; j++) s += row[j];
        y = s * (1.0f / 49.0f);
    }

    // Block reduce sum(y), sum(y*y) over 512 active lanes (idle lanes carry 0).
    float a = y, b = y * y;
    #pragma unroll
    for (int off = 16; off > 0; off >>= 1) {
        a += __shfl_xor_sync(0xffffffffu, a, off);
        b += __shfl_xor_sync(0xffffffffu, b, off);
    }
    const int wid = tid >> 5, lid = tid & 31;
    if (lid == 0) { redA[wid] = a; redB[wid] = b; }
    __syncthreads();
    if (tid < 32) {
        a = redA[tid];
        b = redB[tid];
        #pragma unroll
        for (int off = 16; off > 0; off >>= 1) {
            a += __shfl_xor_sync(0xffffffffu, a, off);
            b += __shfl_xor_sync(0xffffffffu, b, off);
        }
        if (tid == 0) {
            const float m   = a * (1.0f / (float)CCH);
            const float mx2 = b * (1.0f / (float)CCH);
            float var = mx2 - m * m;
            var = var > 0.0f ? var : 0.0f;
            statMI[0] = m;
            statMI[1] = rsqrtf(var + EPS);
        }
    }
    __syncthreads();

    // Gate: exp(-0.5 * C_PARAM * yn^2) with C_PARAM=2 -> exp(-yn^2)
    if (tid < CCH) {
        const float yn = (y - statMI[0]) * statMI[1];
        gateS[tid] = __expf(-yn * yn);
    }
    __syncthreads();

    // Phase 3: multiply from SMEM and store, coalesced float4.
    // Incremental divmod: (q, r) = divmod(4*i, 49); stride adds (QSTEP, RSTEP).
    {
        int e = tid * 4;
        int q = e / HW;            // single divide per thread
        int r = e - q * HW;
        #pragma unroll 2
        for (int i = tid; i < NVEC; i += NTHR) {
            float4 v = tile4[i];
            const float g0 = gateS[q];
            const float g1 = gateS[q + 1];   // padded; safe even at q=511
            v.x *= g0;
            v.y *= (r + 1 >= HW) ? g1 : g0;
            v.z *= (r + 2 >= HW) ? g1 : g0;
            v.w *= (r + 3 >= HW) ? g1 : g0;
            xout[i] = v;
            q += QSTEP; r += RSTEP;
            if (r >= HW) { r -= HW; q += 1; }
        }
    }
}

extern "C" void kernel_launch(void* const* d_in, const int* in_sizes, int n_in,
                              void* d_out, int out_size) {
    const float* x = (const float*)d_in[0];
    float* out = (float*)d_out;
    const int N = in_sizes[0] / CHW;   // 2048

    cudaFuncSetAttribute(gate_fused_kernel,
                         cudaFuncAttributeMaxDynamicSharedMemorySize,
                         CHW * (int)sizeof(float));
    gate_fused_kernel<<<N, NTHR, CHW * sizeof(float)>>>(x, out);
}

// round 4
// speedup vs baseline: 1.1519x; 1.1038x over previous
#include <cuda_runtime.h>
#include <cstdint>

#define CCH   512
#define HW    49
#define CHW   (CCH * HW)          // 25088 floats per sample
#define NVEC  (CHW / 4)           // 6272 float4 per sample
#define NTHR  1024
#define EPS   1e-5f
#define TILE_BYTES (CHW * 4)      // 100352 B, multiple of 16

// Per-thread stride in float4s = NTHR; in floats = 4096 = 83*49 + 29
#define QSTEP 83
#define RSTEP 29

__device__ __forceinline__ uint32_t smem_u32(const void* p) {
    return (uint32_t)__cvta_generic_to_shared(p);
}

__device__ __forceinline__ void bulk_load(uint32_t dst, const void* src,
                                          uint32_t bytes, uint32_t mbar) {
    asm volatile(
        "cp.async.bulk.shared::cta.global.mbarrier::complete_tx::bytes [%0], [%1], %2, [%3];"
        :: "r"(dst), "l"(src), "r"(bytes), "r"(mbar) : "memory");
}

__device__ __forceinline__ void mbar_expect_tx(uint32_t mbar, uint32_t bytes) {
    asm volatile("mbarrier.arrive.expect_tx.shared.b64 _, [%0], %1;"
                 :: "r"(mbar), "r"(bytes) : "memory");
}

__device__ __forceinline__ void mbar_wait(uint32_t mbar, uint32_t parity) {
    asm volatile(
        "{\n\t"
        ".reg .pred P;\n\t"
        "WAIT_LP_%=:\n\t"
        "mbarrier.try_wait.parity.acquire.cta.shared::cta.b64 P, [%0], %1, 0x989680;\n\t"
        "@P bra.uni WAIT_DN_%=;\n\t"
        "bra.uni WAIT_LP_%=;\n\t"
        "WAIT_DN_%=:\n\t"
        "}"
        :: "r"(mbar), "r"(parity) : "memory");
}

__global__ __launch_bounds__(NTHR, 1)
void gate_pipe_kernel(const float* __restrict__ x, float* __restrict__ out, int N) {
    extern __shared__ float smem[];           // 2 * CHW floats (2 * 100,352 B)
    float* const tiles[2] = { smem, smem + CHW };
    __shared__ float gateS[CCH + 8];
    __shared__ float redA[32];
    __shared__ float redB[32];
    __shared__ float statMI[2];               // [0]=mean, [1]=inv_std
    __shared__ __align__(8) unsigned long long mbar_store[2];

    const int tid = threadIdx.x;
    const uint32_t mb0 = smem_u32(&mbar_store[0]);
    const uint32_t mb1 = smem_u32(&mbar_store[1]);

    if (tid == 0) {
        asm volatile("mbarrier.init.shared.b64 [%0], 1;" :: "r"(mb0) : "memory");
        asm volatile("mbarrier.init.shared.b64 [%0], 1;" :: "r"(mb1) : "memory");
    }
    __syncthreads();

    const int stride = gridDim.x;
    const int s0 = blockIdx.x;
    if (s0 >= N) return;

    // Prologue: kick off load of first sample into buffer 0.
    if (tid == 0) {
        mbar_expect_tx(mb0, TILE_BYTES);
        bulk_load(smem_u32(tiles[0]), x + (size_t)s0 * CHW, TILE_BYTES, mb0);
    }

    int ph0 = 0, ph1 = 0;
    int idx = 0;
    for (int s = s0; s < N; s += stride, idx++) {
        const int b = idx & 1;
        const float* tile = tiles[b];
        const uint32_t mb_cur = b ? mb1 : mb0;

        // Prefetch next sample into the other buffer (its reads finished at
        // the end of the previous iteration's __syncthreads).
        const int sn = s + stride;
        if (sn < N && tid == 0) {
            const uint32_t mb_nxt = b ? mb0 : mb1;
            mbar_expect_tx(mb_nxt, TILE_BYTES);
            bulk_load(smem_u32(tiles[b ^ 1]), x + (size_t)sn * CHW, TILE_BYTES, mb_nxt);
        }

        // Wait for current buffer's TMA to land.
        mbar_wait(mb_cur, b ? ph1 : ph0);
        if (b) ph1 ^= 1; else ph0 ^= 1;

        // Phase 2: per-channel spatial mean (threads 0..511, one channel each).
        float y = 0.0f;
        if (tid < CCH) {
            float acc = 0.0f;
            const float* row = tile + tid * HW;
            #pragma unroll
            for (int j = 0; j < HW; j++) acc += row[j];
            y = acc * (1.0f / 49.0f);
        }

        // Block reduce sum(y), sum(y*y).
        float a = y, bb = y * y;
        #pragma unroll
        for (int off = 16; off > 0; off >>= 1) {
            a  += __shfl_xor_sync(0xffffffffu, a, off);
            bb += __shfl_xor_sync(0xffffffffu, bb, off);
        }
        const int wid = tid >> 5, lid = tid & 31;
        if (lid == 0) { redA[wid] = a; redB[wid] = bb; }
        __syncthreads();
        if (tid < 32) {
            a  = redA[tid];
            bb = redB[tid];
            #pragma unroll
            for (int off = 16; off > 0; off >>= 1) {
                a  += __shfl_xor_sync(0xffffffffu, a, off);
                bb += __shfl_xor_sync(0xffffffffu, bb, off);
            }
            if (tid == 0) {
                const float m   = a  * (1.0f / (float)CCH);
                const float mx2 = bb * (1.0f / (float)CCH);
                float var = mx2 - m * m;
                var = var > 0.0f ? var : 0.0f;
                statMI[0] = m;
                statMI[1] = rsqrtf(var + EPS);
            }
        }
        __syncthreads();

        // Gate: exp(-0.5*C*yn^2), C=2 -> exp(-yn^2)
        if (tid < CCH) {
            const float yn = (y - statMI[0]) * statMI[1];
            gateS[tid] = __expf(-yn * yn);
        }
        __syncthreads();

        // Phase 3: multiply from SMEM, coalesced float4 STG.
        {
            float4* __restrict__ xout =
                reinterpret_cast<float4*>(out + (size_t)s * CHW);
            const float4* tile4 = reinterpret_cast<const float4*>(tile);
            int e = tid * 4;
            int q = e / HW;          // single divide per thread per sample
            int r = e - q * HW;
            #pragma unroll 2
            for (int i = tid; i < NVEC; i += NTHR) {
                float4 v = tile4[i];
                const float g0 = gateS[q];
                const float g1 = gateS[q + 1];   // padded; safe at q=511
                v.x *= g0;
                v.y *= (r + 1 >= HW) ? g1 : g0;
                v.z *= (r + 2 >= HW) ? g1 : g0;
                v.w *= (r + 3 >= HW) ? g1 : g0;
                xout[i] = v;
                q += QSTEP; r += RSTEP;
                if (r >= HW) { r -= HW; q += 1; }
            }
        }

        // All threads done reading this buffer + gateS before the next
        // iteration prefetches into it / overwrites gate.
        __syncthreads();
    }
}

extern "C" void kernel_launch(void* const* d_in, const int* in_sizes, int n_in,
                              void* d_out, int out_size) {
    const float* x = (const float*)d_in[0];
    float* out = (float*)d_out;
    const int N = in_sizes[0] / CHW;   // 2048

    int sm_count = 0;
    if (cudaDeviceGetAttribute(&sm_count, cudaDevAttrMultiProcessorCount, 0)
        != cudaSuccess || sm_count <= 0)
        sm_count = 148;
    if (sm_count > N) sm_count = N;

    const int dyn_smem = 2 * TILE_BYTES;   // 200,704 B
    cudaFuncSetAttribute(gate_pipe_kernel,
                         cudaFuncAttributeMaxDynamicSharedMemorySize, dyn_smem);
    gate_pipe_kernel<<<sm_count, NTHR, dyn_smem>>>(x, out, N);
}

// round 5
// speedup vs baseline: 1.1938x; 1.0364x over previous
#include <cuda_runtime.h>
#include <cstdint>

#define CCH   512
#define HW    49
#define CHW   (CCH * HW)          // 25088 floats per sample
#define NVEC  (CHW / 4)           // 6272 float4 per sample
#define NTHR  1024
#define EPS   1e-5f
#define TILE_BYTES (CHW * 4)      // 100352 B, 16B-multiple

// Per-thread stride in float4s = NTHR; in floats = 4096 = 83*49 + 29
#define QSTEP 83
#define RSTEP 29

__device__ __forceinline__ uint32_t smem_u32(const void* p) {
    return (uint32_t)__cvta_generic_to_shared(p);
}

__device__ __forceinline__ void bulk_load(uint32_t dst, const void* src,
                                          uint32_t bytes, uint32_t mbar) {
    asm volatile(
        "cp.async.bulk.shared::cta.global.mbarrier::complete_tx::bytes [%0], [%1], %2, [%3];"
        :: "r"(dst), "l"(src), "r"(bytes), "r"(mbar) : "memory");
}

__device__ __forceinline__ void bulk_store(void* dst, uint32_t src, uint32_t bytes) {
    asm volatile(
        "cp.async.bulk.global.shared::cta.bulk_group [%0], [%1], %2;"
        :: "l"(dst), "r"(src), "r"(bytes) : "memory");
}

__device__ __forceinline__ void mbar_expect_tx(uint32_t mbar, uint32_t bytes) {
    asm volatile("mbarrier.arrive.expect_tx.shared.b64 _, [%0], %1;"
                 :: "r"(mbar), "r"(bytes) : "memory");
}

__device__ __forceinline__ void mbar_wait(uint32_t mbar, uint32_t parity) {
    asm volatile(
        "{\n\t"
        ".reg .pred P;\n\t"
        "WAIT_LP_%=:\n\t"
        "mbarrier.try_wait.parity.acquire.cta.shared::cta.b64 P, [%0], %1, 0x989680;\n\t"
        "@P bra.uni WAIT_DN_%=;\n\t"
        "bra.uni WAIT_LP_%=;\n\t"
        "WAIT_DN_%=:\n\t"
        "}"
        :: "r"(mbar), "r"(parity) : "memory");
}

__global__ __launch_bounds__(NTHR, 1)
void gate_pipe_kernel(const float* __restrict__ x, float* __restrict__ out, int N) {
    extern __shared__ float smem[];           // 2 * CHW floats (2 * 100,352 B)
    float* const tiles[2] = { smem, smem + CHW };
    __shared__ float part[NTHR];
    __shared__ float gateS[CCH + 8];
    __shared__ float redA[32];
    __shared__ float redB[32];
    __shared__ float statMI[2];               // [0]=mean, [1]=inv_std
    __shared__ __align__(8) unsigned long long mbar_store[2];

    const int tid = threadIdx.x;
    const uint32_t mb0 = smem_u32(&mbar_store[0]);
    const uint32_t mb1 = smem_u32(&mbar_store[1]);

    if (tid == 0) {
        asm volatile("mbarrier.init.shared.b64 [%0], 1;" :: "r"(mb0) : "memory");
        asm volatile("mbarrier.init.shared.b64 [%0], 1;" :: "r"(mb1) : "memory");
    }
    __syncthreads();

    const int stride = gridDim.x;
    const int s0 = blockIdx.x;
    if (s0 >= N) return;

    // Prologue: load first sample into buffer 0.
    if (tid == 0) {
        mbar_expect_tx(mb0, TILE_BYTES);
        bulk_load(smem_u32(tiles[0]), x + (size_t)s0 * CHW, TILE_BYTES, mb0);
    }

    int ph0 = 0, ph1 = 0;
    int idx = 0;
    for (int s = s0; s < N; s += stride, idx++) {
        const int b = idx & 1;
        float* tile = tiles[b];
        const uint32_t mb_cur = b ? mb1 : mb0;

        // Refill the other buffer with sample s+stride. Its previous tenant
        // (sample s-stride) was committed as a bulk-store group last
        // iteration: wait for that group to drain before overwriting.
        const int sn = s + stride;
        if (sn < N && tid == 0) {
            asm volatile("cp.async.bulk.wait_group 0;" ::: "memory");
            const uint32_t mb_nxt = b ? mb0 : mb1;
            mbar_expect_tx(mb_nxt, TILE_BYTES);
            bulk_load(smem_u32(tiles[b ^ 1]), x + (size_t)sn * CHW, TILE_BYTES, mb_nxt);
        }

        // Wait for current buffer's TMA load.
        mbar_wait(mb_cur, b ? ph1 : ph0);
        if (b) ph1 ^= 1; else ph0 ^= 1;

        // Phase 2: per-channel spatial sums, all 1024 threads.
        // Thread pair (c, c+512) splits channel c's 49 elems as 25 + 24.
        {
            const int c    = tid & (CCH - 1);
            const int half = tid >> 9;                 // 0 or 1
            const float* row = tile + c * HW + half * 25;
            const int cnt  = half ? 24 : 25;
            float sacc = 0.0f;
            #pragma unroll 5
            for (int j = 0; j < cnt; j++) sacc += row[j];
            part[tid] = sacc;
        }
        __syncthreads();

        float y = 0.0f;
        if (tid < CCH) y = (part[tid] + part[tid + CCH]) * (1.0f / 49.0f);

        // Block reduce sum(y), sum(y*y) (idle lanes carry 0).
        float a = y, bb = y * y;
        #pragma unroll
        for (int off = 16; off > 0; off >>= 1) {
            a  += __shfl_xor_sync(0xffffffffu, a, off);
            bb += __shfl_xor_sync(0xffffffffu, bb, off);
        }
        const int wid = tid >> 5, lid = tid & 31;
        if (lid == 0) { redA[wid] = a; redB[wid] = bb; }
        __syncthreads();
        if (tid < 32) {
            a  = redA[tid];
            bb = redB[tid];
            #pragma unroll
            for (int off = 16; off > 0; off >>= 1) {
                a  += __shfl_xor_sync(0xffffffffu, a, off);
                bb += __shfl_xor_sync(0xffffffffu, bb, off);
            }
            if (tid == 0) {
                const float m   = a  * (1.0f / (float)CCH);
                const float mx2 = bb * (1.0f / (float)CCH);
                float var = mx2 - m * m;
                var = var > 0.0f ? var : 0.0f;
                statMI[0] = m;
                statMI[1] = rsqrtf(var + EPS);
            }
        }
        __syncthreads();

        // Gate: exp(-0.5*C*yn^2), C=2 -> exp(-yn^2)
        if (tid < CCH) {
            const float yn = (y - statMI[0]) * statMI[1];
            gateS[tid] = __expf(-yn * yn);
        }
        __syncthreads();

        // Phase 3: multiply in place in SMEM (LDS -> FMUL -> STS).
        {
            float4* tile4 = reinterpret_cast<float4*>(tile);
            int e = tid * 4;
            int q = e / HW;          // one divide per thread per sample
            int r = e - q * HW;
            #pragma unroll 2
            for (int i = tid; i < NVEC; i += NTHR) {
                float4 v = tile4[i];
                const float g0 = gateS[q];
                const float g1 = gateS[q + 1];   // padded; safe at q=511
                v.x *= g0;
                v.y *= (r + 1 >= HW) ? g1 : g0;
                v.z *= (r + 2 >= HW) ? g1 : g0;
                v.w *= (r + 3 >= HW) ? g1 : g0;
                tile4[i] = v;
                q += QSTEP; r += RSTEP;
                if (r >= HW) { r -= HW; q += 1; }
            }
        }
        __syncthreads();

        // Async bulk store of the gated tile; drains while we start the
        // next sample's reduce. fence orders the STS above (generic proxy)
        // before the bulk-store read (async proxy).
        if (tid == 0) {
            asm volatile("fence.proxy.async.shared::cta;" ::: "memory");
            bulk_store(out + (size_t)s * CHW, smem_u32(tile), TILE_BYTES);
            asm volatile("cp.async.bulk.commit_group;" ::: "memory");
        }
        // No trailing __syncthreads needed: buffer b is only touched again
        // two iterations from now, after wait_group 0 + mbar_wait.
    }

    // Drain the final store group before exit.
    if (tid == 0)
        asm volatile("cp.async.bulk.wait_group 0;" ::: "memory");
}

extern "C" void kernel_launch(void* const* d_in, const int* in_sizes, int n_in,
                              void* d_out, int out_size) {
    const float* x = (const float*)d_in[0];
    float* out = (float*)d_out;
    const int N = in_sizes[0] / CHW;   // 2048

    int sm_count = 0;
    if (cudaDeviceGetAttribute(&sm_count, cudaDevAttrMultiProcessorCount, 0)
        != cudaSuccess || sm_count <= 0)
        sm_count = 148;
    if (sm_count > N) sm_count = N;

    const int dyn_smem = 2 * TILE_BYTES;   // 200,704 B
    cudaFuncSetAttribute(gate_pipe_kernel,
                         cudaFuncAttributeMaxDynamicSharedMemorySize, dyn_smem);
    gate_pipe_kernel<<<sm_count, NTHR, dyn_smem>>>(x, out, N);
}